// round 11
// baseline (speedup 1.0000x reference)
#include <cuda_runtime.h>
#include <cuda.h>
#include <math.h>
#include <stdint.h>

// Fixed shape: H=1024, B=64, T=1024
#define BB 64
#define TS 1024
#define HS 1024
#define TCH 8                        // t per tile
#define NTILES 8192                  // 64 b * 128 t-chunks
#define GRIDN 304                    // 2 CTAs per SM
#define NTHR 512
#define DEPTH 3
#define TILE_FLOATS (HS * TCH)       // 8192
#define TILE_BYTES (TILE_FLOATS * 4) // 32 KB
#define L2E 1.44269504088896340736f

// dynamic smem layout (floats)
#define F_DH   (DEPTH * TILE_FLOATS)      // dh slice: 1024 floats
#define F_SRED (F_DH + HS)                // A/B/C/D: [4][16 w][8 t] = 512 floats
#define F_END  (F_SRED + 512)
#define B_MBAR (F_END * 4)
#define SMEM_BYTES (B_MBAR + DEPTH * 8)   // ~102 KB -> 2 CTAs/SM

__device__ __forceinline__ uint32_t smem_u32(const void* p) {
    return (uint32_t)__cvta_generic_to_shared(p);
}
__device__ __forceinline__ void mbar_init(uint32_t a, uint32_t cnt) {
    asm volatile("mbarrier.init.shared.b64 [%0], %1;" :: "r"(a), "r"(cnt) : "memory");
}
#define MB_WAIT(addr, parity) do {                                              \
    uint32_t _m = (addr), _p = (parity), _d;                                    \
    asm volatile("{\n\t.reg .pred p;\n\t"                                       \
        "mbarrier.try_wait.parity.acquire.cta.shared::cta.b64 p, [%1], %2;\n\t" \
        "selp.b32 %0, 1, 0, p;\n\t}" : "=r"(_d) : "r"(_m), "r"(_p) : "memory"); \
    if (!_d) {                                                                  \
        asm volatile("{\n\t.reg .pred P1;\n\tW%=:\n\t"                          \
            "mbarrier.try_wait.parity.acquire.cta.shared::cta.b64 P1, [%0], %1, 0x989680;\n\t" \
            "@P1 bra.uni D%=;\n\tbra.uni W%=;\n\tD%=:\n\t}"                     \
            :: "r"(_m), "r"(_p) : "memory");                                    \
    }                                                                           \
} while (0)

// One 32KB tile (tile id m) into ring slot s: expect_tx + 4 x 3D TMA.
__device__ __forceinline__ void tma_issue(const CUtensorMap& tmap, uint32_t sb,
                                          uint32_t MB, int s, int m) {
    const int c = m & 127, b = m >> 7;
    const uint32_t mb = MB + (uint32_t)s * 8;
    asm volatile("mbarrier.arrive.expect_tx.shared.b64 _, [%0], %1;"
                 :: "r"(mb), "r"((uint32_t)TILE_BYTES) : "memory");
    const uint32_t dst = sb + (uint32_t)s * TILE_BYTES;
    #pragma unroll
    for (int k = 0; k < 4; ++k) {
        asm volatile(
            "cp.async.bulk.tensor.3d.shared::cta.global.tile.mbarrier::complete_tx::bytes "
            "[%0], [%1, {%2, %3, %4}], [%5];"
            :: "r"(dst + (uint32_t)k * 8192), "l"(&tmap),
               "r"(c * TCH), "r"(b), "r"(k * 256), "r"(mb) : "memory");
    }
}

// In-register 8x8 transpose-reduce over lanes' low-3 bits (hw = lane & 7).
__device__ __forceinline__ void tr_reduce8(float* a, int hw) {
    #pragma unroll
    for (int s = 4; s >= 1; s >>= 1) {
        const bool up = (hw & s) != 0;
        #pragma unroll
        for (int i = 0; i < s; ++i) {
            const float give = up ? a[i] : a[i + s];
            const float keep = up ? a[i + s] : a[i];
            const float got  = __shfl_xor_sync(0xffffffffu, give, s);
            a[i] = keep + got;
        }
    }
}

__global__ void __launch_bounds__(1024)
zero_out(float* __restrict__ out) {
    out[blockIdx.x * 1024 + threadIdx.x] = 0.0f;
}

__global__ void __launch_bounds__(NTHR, 2)
attn_main(const __grid_constant__ CUtensorMap tmap,
          const float* __restrict__ dh, float* __restrict__ out) {
    extern __shared__ float smem[];
    const uint32_t sb = smem_u32(smem);
    const uint32_t MB = sb + B_MBAR;
    float* dhs   = smem + F_DH;
    float* sredA = smem + F_SRED;        // [16 w][8 t]
    float* sredB = sredA + 128;
    float* sredC = sredB + 128;
    float* sredD = sredC + 128;

    const int tid = threadIdx.x;
    const int w = tid >> 5, l = tid & 31;
    const int t = l & 7, hr = l >> 3;    // hr 0..3
    const int rg = w * 4 + hr;           // row residue: rows rg + 64*i, i < 16

    const int start = (int)(((long long)blockIdx.x * NTILES) / GRIDN);
    const int end   = (int)(((long long)(blockIdx.x + 1) * NTILES) / GRIDN);
    const int nt    = end - start;

    if (tid == 0)
        for (int s = 0; s < DEPTH; ++s) mbar_init(MB + s * 8, 1);
    __syncthreads();

    if (tid == 0)
        for (int k = 0; k < DEPTH && k < nt; ++k)
            tma_issue(tmap, sb, MB, k, start + k);

    float acc[16];
    #pragma unroll
    for (int i = 0; i < 16; ++i) acc[i] = 0.0f;

    int bcur = -1;
    for (int n = 0; n < nt; ++n) {
        const int m = start + n;
        const int b = m >> 7;
        const int s = n % DEPTH;

        if (b != bcur) {                 // <= 2 times per CTA
            if (bcur >= 0) {
                #pragma unroll
                for (int g = 0; g < 2; ++g) {
                    tr_reduce8(acc + 8 * g, t);
                    atomicAdd(out + bcur * HS + rg + 64 * (8 * g + t), acc[8 * g]);
                }
                #pragma unroll
                for (int i = 0; i < 16; ++i) acc[i] = 0.0f;
            }
            if (tid < 256)
                reinterpret_cast<float4*>(dhs)[tid] =
                    __ldg(reinterpret_cast<const float4*>(dh + b * HS) + tid);
            bcur = b;
            __syncthreads();             // dh visible before use
        }
        MB_WAIT(MB + s * 8, (n / DEPTH) & 1);

        // ---- stat pass: tile slice -> registers, fused dot/max/min ----
        // element (row, t) at tile[row*8 + t]; bank = hr*8 + t = lane id.
        const float* tp = smem + s * TILE_FLOATS + rg * TCH + t;
        const float* dp = dhs + rg;
        float v[16];
        float sp = 0.f, mx = -INFINITY, mn = INFINITY;
        #pragma unroll
        for (int i = 0; i < 16; ++i) {
            v[i] = tp[i * 64 * TCH];
            sp = fmaf(v[i], dp[i * 64], sp);
            mx = fmaxf(mx, v[i]);
            mn = fminf(mn, v[i]);
        }
        // reduce across the 4 hr groups (lane bits 3,4)
        sp += __shfl_xor_sync(~0u, sp, 8);
        sp += __shfl_xor_sync(~0u, sp, 16);
        mx = fmaxf(mx, __shfl_xor_sync(~0u, mx, 8));
        mx = fmaxf(mx, __shfl_xor_sync(~0u, mx, 16));
        mn = fminf(mn, __shfl_xor_sync(~0u, mn, 8));
        mn = fminf(mn, __shfl_xor_sync(~0u, mn, 16));
        if (l < 8) {
            sredA[w * 8 + l] = sp;
            sredB[w * 8 + l] = mx;
            sredC[w * 8 + l] = mn;
        }
        __syncthreads();   // #1: stats posted AND slot s fully consumed

        // refill slot s (now provably free)
        if (tid == 0 && n + DEPTH < nt)
            tma_issue(tmap, sb, MB, s, m + DEPTH);

        // every thread folds the 16 warp-partials for its t (broadcast LDS)
        float sc = 0.f, X = -INFINITY, N = INFINITY;
        #pragma unroll
        for (int w2 = 0; w2 < 16; ++w2) {
            sc += sredA[w2 * 8 + t];
            X = fmaxf(X, sredB[w2 * 8 + t]);
            N = fminf(N, sredC[w2 * 8 + t]);
        }
        const float M   = (sc >= 0.f) ? X * sc : N * sc;  // exact max_h(v*s)
        const float scF = sc * L2E;
        const float MF  = M * L2E;

        // ---- exp2 on registers + denominator ----
        float ds = 0.f;
        #pragma unroll
        for (int i = 0; i < 16; ++i) {
            v[i] = exp2f(fmaf(v[i], scF, -MF));
            ds += v[i];
        }
        ds += __shfl_xor_sync(~0u, ds, 8);
        ds += __shfl_xor_sync(~0u, ds, 16);
        if (l < 8) sredD[w * 8 + l] = ds;
        __syncthreads();   // #2: denoms posted

        float d = 0.f;
        #pragma unroll
        for (int w2 = 0; w2 < 16; ++w2) d += sredD[w2 * 8 + t];
        const float inv = 1.0f / d;

        #pragma unroll
        for (int i = 0; i < 16; ++i)
            acc[i] = fmaf(v[i], inv, acc[i]);
    }

    // final flush for the last b
    if (bcur >= 0) {
        #pragma unroll
        for (int g = 0; g < 2; ++g) {
            tr_reduce8(acc + 8 * g, t);
            atomicAdd(out + bcur * HS + rg + 64 * (8 * g + t), acc[8 * g]);
        }
    }
}

extern "C" void kernel_launch(void* const* d_in, const int* in_sizes, int n_in,
                              void* d_out, int out_size) {
    const float* dh  = (const float*)d_in[0];
    const float* enc = (const float*)d_in[1];
    if (n_in >= 2 && in_sizes[0] > in_sizes[1]) {
        enc = (const float*)d_in[0];
        dh  = (const float*)d_in[1];
    }
    float* out = (float*)d_out;

    typedef CUresult (*EncodeFn)(
        CUtensorMap*, CUtensorMapDataType, cuuint32_t, void*,
        const cuuint64_t*, const cuuint64_t*, const cuuint32_t*, const cuuint32_t*,
        CUtensorMapInterleave, CUtensorMapSwizzle, CUtensorMapL2promotion,
        CUtensorMapFloatOOBfill);
    void* fp = nullptr;
    cudaDriverEntryPointQueryResult qres;
#if CUDART_VERSION >= 12050
    cudaGetDriverEntryPointByVersion("cuTensorMapEncodeTiled", &fp, 12030,
                                     cudaEnableDefault, &qres);
#else
    cudaGetDriverEntryPoint("cuTensorMapEncodeTiled", &fp, cudaEnableDefault, &qres);
#endif
    CUtensorMap tmap;
    {
        EncodeFn fn = (EncodeFn)fp;
        cuuint64_t dims[3]    = {TS, BB, HS};
        cuuint64_t strides[2] = {TS * 4ull, (cuuint64_t)BB * TS * 4ull};
        cuuint32_t box[3]     = {TCH, 1, 256};
        cuuint32_t es[3]      = {1, 1, 1};
        fn(&tmap, CU_TENSOR_MAP_DATA_TYPE_FLOAT32, 3, (void*)enc,
           dims, strides, box, es,
           CU_TENSOR_MAP_INTERLEAVE_NONE, CU_TENSOR_MAP_SWIZZLE_NONE,
           CU_TENSOR_MAP_L2_PROMOTION_L2_128B, CU_TENSOR_MAP_FLOAT_OOB_FILL_NONE);
    }

    cudaFuncSetAttribute(attn_main,
                         cudaFuncAttributeMaxDynamicSharedMemorySize, SMEM_BYTES);
    zero_out<<<64, 1024>>>(out);
    attn_main<<<GRIDN, NTHR, SMEM_BYTES>>>(tmap, dh, out);
}

// round 12
// speedup vs baseline: 1.2443x; 1.2443x over previous
#include <cuda_runtime.h>
#include <cuda.h>
#include <math.h>
#include <stdint.h>

// Fixed shape: H=1024, B=64, T=1024
#define BB 64
#define TS 1024
#define HS 1024
#define TCH 16                       // t per tile
#define NTILES 4096                  // 64 b * 64 t-chunks
#define GRIDN 152
#define NTHR 1024
#define DEPTH 3
#define TILE_FLOATS (HS * TCH)       // 16384
#define TILE_BYTES (TILE_FLOATS * 4) // 64 KB
#define L2E 1.44269504088896340736f

// dynamic smem layout (floats)
#define F_DH   (DEPTH * TILE_FLOATS)      // dh slice: 1024 floats
#define F_SRED (F_DH + HS)                // A/B/C/D: [4][32 w][16 t] = 2048 floats
#define F_FIN  (F_SRED + 2048)            // sc[16] | X[16] | N[16] | inv[16]
#define F_END  (F_FIN + 64)
#define B_MBAR (F_END * 4)
#define SMEM_BYTES (B_MBAR + DEPTH * 8)   // ~209 KB

__device__ __forceinline__ uint32_t smem_u32(const void* p) {
    return (uint32_t)__cvta_generic_to_shared(p);
}
__device__ __forceinline__ void mbar_init(uint32_t a, uint32_t cnt) {
    asm volatile("mbarrier.init.shared.b64 [%0], %1;" :: "r"(a), "r"(cnt) : "memory");
}
#define MB_WAIT(addr, parity) do {                                              \
    uint32_t _m = (addr), _p = (parity), _d;                                    \
    asm volatile("{\n\t.reg .pred p;\n\t"                                       \
        "mbarrier.try_wait.parity.acquire.cta.shared::cta.b64 p, [%1], %2;\n\t" \
        "selp.b32 %0, 1, 0, p;\n\t}" : "=r"(_d) : "r"(_m), "r"(_p) : "memory"); \
    if (!_d) {                                                                  \
        asm volatile("{\n\t.reg .pred P1;\n\tW%=:\n\t"                          \
            "mbarrier.try_wait.parity.acquire.cta.shared::cta.b64 P1, [%0], %1, 0x989680;\n\t" \
            "@P1 bra.uni D%=;\n\tbra.uni W%=;\n\tD%=:\n\t}"                     \
            :: "r"(_m), "r"(_p) : "memory");                                    \
    }                                                                           \
} while (0)

// One 64KB tile (tile id m) into ring slot s: expect_tx + 4 x 3D TMA.
__device__ __forceinline__ void tma_issue(const CUtensorMap& tmap, uint32_t sb,
                                          uint32_t MB, int s, int m) {
    const int c = m & 63, b = m >> 6;
    const uint32_t mb = MB + (uint32_t)s * 8;
    asm volatile("mbarrier.arrive.expect_tx.shared.b64 _, [%0], %1;"
                 :: "r"(mb), "r"((uint32_t)TILE_BYTES) : "memory");
    const uint32_t dst = sb + (uint32_t)s * TILE_BYTES;
    #pragma unroll
    for (int k = 0; k < 4; ++k) {
        asm volatile(
            "cp.async.bulk.tensor.3d.shared::cta.global.tile.mbarrier::complete_tx::bytes "
            "[%0], [%1, {%2, %3, %4}], [%5];"
            :: "r"(dst + (uint32_t)k * 16384), "l"(&tmap),
               "r"(c * TCH), "r"(b), "r"(k * 256), "r"(mb) : "memory");
    }
}

// In-register 16x16 transpose-reduce over half-warp lanes (hw = lane & 15).
// After: a[0] on lane hw = sum over the 16 half-warp lanes of column hw.
__device__ __forceinline__ void tr_reduce16(float* a, int hw) {
    #pragma unroll
    for (int s = 8; s >= 1; s >>= 1) {
        const bool up = (hw & s) != 0;
        #pragma unroll
        for (int i = 0; i < s; ++i) {
            const float give = up ? a[i] : a[i + s];
            const float keep = up ? a[i + s] : a[i];
            const float got  = __shfl_xor_sync(0xffffffffu, give, s);
            a[i] = keep + got;
        }
    }
}

__global__ void __launch_bounds__(1024)
zero_out(float* __restrict__ out) {
    out[blockIdx.x * 1024 + threadIdx.x] = 0.0f;
}

__global__ void __launch_bounds__(NTHR, 1)
attn_main(const __grid_constant__ CUtensorMap tmap,
          const float* __restrict__ dh, float* __restrict__ out) {
    extern __shared__ float smem[];
    const uint32_t sb = smem_u32(smem);
    const uint32_t MB = sb + B_MBAR;
    float* dhs   = smem + F_DH;
    float* sredA = smem + F_SRED;        // [32 w][16 t]
    float* sredB = sredA + 512;
    float* sredC = sredB + 512;
    float* sredD = sredC + 512;
    float* fin   = smem + F_FIN;         // sc | X | N | inv

    const int tid = threadIdx.x;
    const int w = tid >> 5, l = tid & 31;
    const int t = l & 15, hr = l >> 4;
    const int rg = w * 2 + hr;           // rows rg + 64*i, i < 16

    const int start = (int)(((long long)blockIdx.x * NTILES) / GRIDN);
    const int end   = (int)(((long long)(blockIdx.x + 1) * NTILES) / GRIDN);
    const int nt    = end - start;

    if (tid == 0)
        for (int s = 0; s < DEPTH; ++s) mbar_init(MB + s * 8, 1);
    __syncthreads();

    if (tid == 0)
        for (int k = 0; k < DEPTH && k < nt; ++k)
            tma_issue(tmap, sb, MB, k, start + k);

    float acc[16];
    #pragma unroll
    for (int i = 0; i < 16; ++i) acc[i] = 0.0f;

    int bcur = -1;
    for (int n = 0; n < nt; ++n) {
        const int m = start + n;
        const int b = m >> 6;
        const int s = n % DEPTH;

        if (b != bcur) {                 // <= 2 times per CTA
            if (bcur >= 0) {
                tr_reduce16(acc, t);     // acc[0] on lane t = row rg + 64*t
                atomicAdd(out + bcur * HS + rg + 64 * t, acc[0]);
                #pragma unroll
                for (int i = 0; i < 16; ++i) acc[i] = 0.0f;
            }
            if (tid < 256)
                reinterpret_cast<float4*>(dhs)[tid] =
                    __ldg(reinterpret_cast<const float4*>(dh + b * HS) + tid);
            bcur = b;
            __syncthreads();             // dh visible before use
        }
        MB_WAIT(MB + s * 8, (n / DEPTH) & 1);

        // ---- stat pass: tile slice -> registers, fused dot/max/min ----
        // element (row, t) at tile[row*16 + t]; bank = 16*(rg&1) + t = lane id.
        const float* tp = smem + s * TILE_FLOATS + rg * TCH + t;
        const float* dp = dhs + rg;
        float v[16];
        float sp = 0.f, mx = -INFINITY, mn = INFINITY;
        #pragma unroll
        for (int i = 0; i < 16; ++i) {
            v[i] = tp[i * 64 * TCH];
            sp = fmaf(v[i], dp[i * 64], sp);   // dh read: 16-lane broadcast
            mx = fmaxf(mx, v[i]);
            mn = fminf(mn, v[i]);
        }
        // combine the two hr halves (lane bit 4)
        sp += __shfl_xor_sync(~0u, sp, 16);
        mx = fmaxf(mx, __shfl_xor_sync(~0u, mx, 16));
        mn = fminf(mn, __shfl_xor_sync(~0u, mn, 16));
        if (l < 16) {
            sredA[w * 16 + l] = sp;
            sredB[w * 16 + l] = mx;
            sredC[w * 16 + l] = mn;
        }
        __syncthreads();   // #1: stats posted AND slot s fully consumed

        // refill slot s (now provably free)
        if (tid == 0 && n + DEPTH < nt)
            tma_issue(tmap, sb, MB, s, m + DEPTH);

        // warps 0/1/2 fold sum/max/min in parallel, publish raw stats
        if (w < 3 && l < 16) {
            if (w == 0) {
                float sc = 0.f;
                #pragma unroll
                for (int w2 = 0; w2 < 32; ++w2) sc += sredA[w2 * 16 + l];
                fin[l] = sc;
            } else if (w == 1) {
                float X = -INFINITY;
                #pragma unroll
                for (int w2 = 0; w2 < 32; ++w2) X = fmaxf(X, sredB[w2 * 16 + l]);
                fin[16 + l] = X;
            } else {
                float N = INFINITY;
                #pragma unroll
                for (int w2 = 0; w2 < 32; ++w2) N = fminf(N, sredC[w2 * 16 + l]);
                fin[32 + l] = N;
            }
        }
        __syncthreads();   // #2

        // each thread derives scaled stats for its t
        const float sc = fin[t];
        const float X  = fin[16 + t];
        const float N  = fin[32 + t];
        const float M  = (sc >= 0.f) ? X * sc : N * sc;   // exact max_h(v*s)
        const float scF = sc * L2E;
        const float MF  = M * L2E;

        // ---- exp2 on registers + denominator ----
        float ds = 0.f;
        #pragma unroll
        for (int i = 0; i < 16; ++i) {
            v[i] = exp2f(fmaf(v[i], scF, -MF));
            ds += v[i];
        }
        ds += __shfl_xor_sync(~0u, ds, 16);
        if (l < 16) sredD[w * 16 + l] = ds;
        __syncthreads();   // #3: denoms posted

        if (w == 0 && l < 16) {
            float d = 0.f;
            #pragma unroll
            for (int w2 = 0; w2 < 32; ++w2) d += sredD[w2 * 16 + l];
            fin[48 + l] = 1.0f / d;
        }
        __syncthreads();   // #4

        const float inv = fin[48 + t];
        #pragma unroll
        for (int i = 0; i < 16; ++i)
            acc[i] = fmaf(v[i], inv, acc[i]);
    }

    // final flush for the last b
    if (bcur >= 0) {
        tr_reduce16(acc, t);
        atomicAdd(out + bcur * HS + rg + 64 * t, acc[0]);
    }
}

extern "C" void kernel_launch(void* const* d_in, const int* in_sizes, int n_in,
                              void* d_out, int out_size) {
    const float* dh  = (const float*)d_in[0];
    const float* enc = (const float*)d_in[1];
    if (n_in >= 2 && in_sizes[0] > in_sizes[1]) {
        enc = (const float*)d_in[0];
        dh  = (const float*)d_in[1];
    }
    float* out = (float*)d_out;

    typedef CUresult (*EncodeFn)(
        CUtensorMap*, CUtensorMapDataType, cuuint32_t, void*,
        const cuuint64_t*, const cuuint64_t*, const cuuint32_t*, const cuuint32_t*,
        CUtensorMapInterleave, CUtensorMapSwizzle, CUtensorMapL2promotion,
        CUtensorMapFloatOOBfill);
    void* fp = nullptr;
    cudaDriverEntryPointQueryResult qres;
#if CUDART_VERSION >= 12050
    cudaGetDriverEntryPointByVersion("cuTensorMapEncodeTiled", &fp, 12030,
                                     cudaEnableDefault, &qres);
#else
    cudaGetDriverEntryPoint("cuTensorMapEncodeTiled", &fp, cudaEnableDefault, &qres);
#endif
    CUtensorMap tmap;
    {
        EncodeFn fn = (EncodeFn)fp;
        cuuint64_t dims[3]    = {TS, BB, HS};
        cuuint64_t strides[2] = {TS * 4ull, (cuuint64_t)BB * TS * 4ull};
        cuuint32_t box[3]     = {TCH, 1, 256};
        cuuint32_t es[3]      = {1, 1, 1};
        fn(&tmap, CU_TENSOR_MAP_DATA_TYPE_FLOAT32, 3, (void*)enc,
           dims, strides, box, es,
           CU_TENSOR_MAP_INTERLEAVE_NONE, CU_TENSOR_MAP_SWIZZLE_NONE,
           CU_TENSOR_MAP_L2_PROMOTION_L2_128B, CU_TENSOR_MAP_FLOAT_OOB_FILL_NONE);
    }

    cudaFuncSetAttribute(attn_main,
                         cudaFuncAttributeMaxDynamicSharedMemorySize, SMEM_BYTES);
    zero_out<<<64, 1024>>>(out);
    attn_main<<<GRIDN, NTHR, SMEM_BYTES>>>(tmap, dh, out);
}